// round 3
// baseline (speedup 1.0000x reference)
#include <cuda_runtime.h>
#include <cstdint>

#define NB 1024
#define NT 512
#define NL 64
#define NTHR 128   // 2 threads per row: tid = 2*j + h

__device__ __forceinline__ unsigned long long pack2(float a, float b) {
    unsigned long long r;
    asm("mov.b64 %0, {%1,%2};" : "=l"(r) : "f"(a), "f"(b));
    return r;
}
__device__ __forceinline__ void unpack2(unsigned long long v, float& a, float& b) {
    asm("mov.b64 {%0,%1}, %2;" : "=f"(a), "=f"(b) : "l"(v));
}
__device__ __forceinline__ void ffma2(unsigned long long& acc, unsigned long long a,
                                      unsigned long long b) {
    asm("fma.rn.f32x2 %0, %1, %2, %0;" : "+l"(acc) : "l"(a), "l"(b));
}

// w buffer layout: 32 floats (k=0..31), 16B pad, 32 floats (k=32..63).
// Half h reads at byte offset h*144 + q*16 -> the two broadcast addresses of a
// wavefront hit disjoint 4-bank sets (words 4q.. vs 4q+4..): conflict-free.
#define WIDX(j) ((j) < 32 ? (j) : (j) + 4)
#define WSTRIDE 68

__global__ __launch_bounds__(NTHR) void crf_nll_kernel(
    const float* __restrict__ feats,      // [B, T, L] fp32
    const float* __restrict__ trans,      // [L, L] fp32
    const int*   __restrict__ labels,     // [B, T] int32 OR int64 (sniffed)
    float*       __restrict__ out)        // [B] fp32
{
    __shared__ __align__(16) float wbuf[2][WSTRIDE];
    __shared__ float red4[4];

    const int b    = blockIdx.x;
    const int tid  = threadIdx.x;
    const int j    = tid >> 1;            // output row 0..63
    const int h    = tid & 1;             // k-half 0/1
    const int lane = tid & 31;
    const int warp = tid >> 5;

    // ---- E2: exp(trans[j, h*32 .. h*32+31]) as 16 packed f32x2 (32 regs) ----
    unsigned long long E2[16];
    {
        const float2* tr2 = (const float2*)(trans + j * NL + h * 32);
        #pragma unroll
        for (int kk = 0; kk < 16; ++kk) {
            float2 v = tr2[kk];
            E2[kk] = pack2(__expf(v.x), __expf(v.y));   // exp(-10000) -> 0
        }
    }

    // ---- init: w = delta at row 0 (START), C = 0 ----
    if (tid < NL) wbuf[0][WIDX(tid)] = (tid == 0) ? 1.0f : 0.0f;
    __syncthreads();

    const float* fb = feats + (size_t)b * NT * NL;
    float C = 0.0f;
    float fnext = __ldg(fb + NL + j);     // prefetch t=1

    #pragma unroll 1
    for (int t = 1; t < NT; ++t) {
        float f = fnext;
        if (t + 1 < NT) fnext = __ldg(fb + (size_t)(t + 1) * NL + j);
        float ef = __expf(f);

        // partial dot over this thread's k-half: 8 LDS.128 + 16 FFMA2 (2 chains of 8)
        const ulonglong2* wv =
            (const ulonglong2*)((const char*)wbuf[(t - 1) & 1] + h * 144);
        unsigned long long acc0 = 0ull, acc1 = 0ull;
        #pragma unroll
        for (int q = 0; q < 8; ++q) {
            ulonglong2 wq = wv[q];
            ffma2(acc0, E2[2 * q],     wq.x);
            ffma2(acc1, E2[2 * q + 1], wq.y);
        }
        float a0, a1, b0, b1;
        unpack2(acc0, a0, a1);
        unpack2(acc1, b0, b1);
        float p = (a0 + b0) + (a1 + b1);

        // combine the two halves (partner is lane^1, same warp)
        p += __shfl_xor_sync(0xffffffffu, p, 1);
        float u = p * ef;

        // renormalize every 4 steps: C += log(max u), w *= 1/max
        float rs = 1.0f;
        if ((t & 3) == 0) {
            float m = u;
            #pragma unroll
            for (int o = 16; o; o >>= 1)
                m = fmaxf(m, __shfl_xor_sync(0xffffffffu, m, o));
            if (lane == 0) red4[warp] = m;
            __syncthreads();
            float mx = fmaxf(fmaxf(red4[0], red4[1]), fmaxf(red4[2], red4[3]));
            C += __logf(mx);
            rs = __frcp_rn(mx);
        }
        if (h == 0) wbuf[t & 1][WIDX(j)] = u * rs;
        __syncthreads();
    }

    // ---- log_Z = C + log(sum_j w[j]) ----
    float s = (tid < NL) ? wbuf[(NT - 1) & 1][WIDX(tid)] : 0.0f;
    #pragma unroll
    for (int o = 16; o; o >>= 1) s += __shfl_xor_sync(0xffffffffu, s, o);
    if (lane == 0) red4[warp] = s;
    __syncthreads();
    float logZ = C + __logf(((red4[0] + red4[1]) + (red4[2] + red4[3])));
    __syncthreads();   // red4 reused below

    // ---- gold path score ----
    const int* li = labels;
    bool i64 = ((li[1] | li[3] | li[5] | li[7] | li[9] | li[11] | li[13] | li[15]) == 0);
    const long long* ll = (const long long*)labels;

    float g = 0.0f;
    for (int t = 1 + tid; t < NT; t += NTHR) {
        int curt, prv;
        if (i64) {
            curt = (int)ll[(size_t)b * NT + t];
            prv  = (int)ll[(size_t)b * NT + t - 1];
        } else {
            curt = li[(size_t)b * NT + t];
            prv  = li[(size_t)b * NT + t - 1];
        }
        g += trans[curt * NL + prv] + fb[(size_t)t * NL + curt];
    }
    #pragma unroll
    for (int o = 16; o; o >>= 1) g += __shfl_xor_sync(0xffffffffu, g, o);
    if (lane == 0) red4[warp] = g;
    __syncthreads();

    if (tid == 0) out[b] = logZ - ((red4[0] + red4[1]) + (red4[2] + red4[3]));
}

extern "C" void kernel_launch(void* const* d_in, const int* in_sizes, int n_in,
                              void* d_out, int out_size) {
    const float* feats  = (const float*)d_in[0];
    const float* trans  = (const float*)d_in[1];
    const int*   labels = (const int*)d_in[2];
    float*       out    = (float*)d_out;
    crf_nll_kernel<<<NB, NTHR>>>(feats, trans, labels, out);
}